// round 5
// baseline (speedup 1.0000x reference)
#include <cuda_runtime.h>

#define BLOCK 128
#define PAIRS 64                      // output pairs per block
#define OUTB  128                     // outputs per block -> grid 2048
#define HALO_L 10
#define TILE 144                      // need 128 + 10 + 5 = 143

typedef unsigned long long u64;

static __device__ __forceinline__ u64 pk2(float a, float b) {
    u64 v; asm("mov.b64 %0,{%1,%2};" : "=l"(v) : "f"(a), "f"(b)); return v;
}
static __device__ __forceinline__ void up2(u64 v, float& a, float& b) {
    asm("mov.b64 {%0,%1},%2;" : "=f"(a), "=f"(b) : "l"(v));
}
static __device__ __forceinline__ u64 fma2(u64 a, u64 b, u64 c) {
    u64 d; asm("fma.rn.f32x2 %0,%1,%2,%3;" : "=l"(d) : "l"(a), "l"(b), "l"(c)); return d;
}
static __device__ __forceinline__ float fsqrt_ap(float x) {
    float r; asm("sqrt.approx.f32 %0,%1;" : "=f"(r) : "f"(x)); return r;
}

// Merged coefficient table: sQ[(l*7+e3)*8 + k] packed (re,im); e3 = e+3, e in [-3,3]:
//   e=0  : a[k,l] + b[k,l,0] + c[k,l,0]
//   e=-m : b[k,l,m]   (envelope at n-l-m)
//   e=+m : c[k,l,m]   (envelope at n-l+m)
// sC0[l] = sum over e3 of the k=0 coefficient (seeds the per-l accumulator).
__global__ __launch_bounds__(BLOCK, 8)
void gmp_kernel(const float2* __restrict__ x,
                const float* __restrict__ ar, const float* __restrict__ ai,
                const float* __restrict__ br, const float* __restrict__ bi,
                const float* __restrict__ cr, const float* __restrict__ ci,
                float2* __restrict__ y, int N) {
    __shared__ float2 sx[TILE];
    __shared__ float  sr[TILE];
    __shared__ __align__(16) u64 sQ[448];
    __shared__ u64 sC0[8];
    __shared__ float4 sP[PAIRS];

    const int t = threadIdx.x;
    const int base = blockIdx.x * OUTB;

    // Build merged coefficient table (small; ar/br/.. are L2-hot)
    for (int i = t; i < 448; i += BLOCK) {
        int k  = i & 7;
        int e3 = (i >> 3) % 7;
        int l  = i / 56;
        int kl = k * 8 + l;                 // a[k][l], row-major (8,8)
        float re, im;
        if (e3 == 3) {
            re = ar[kl] + br[kl * 4] + cr[kl * 4];
            im = ai[kl] + bi[kl * 4] + ci[kl * 4];
        } else if (e3 < 3) {
            int m = 3 - e3;
            re = br[kl * 4 + m]; im = bi[kl * 4 + m];
        } else {
            int m = e3 - 3;
            re = cr[kl * 4 + m]; im = ci[kl * 4 + m];
        }
        sQ[(l * 7 + e3) * 8 + k] = pk2(re, im);
    }
    if (t < 8) {
        int l = t;
        float re = ar[l], im = ai[l];
        #pragma unroll
        for (int m = 0; m < 4; m++) {
            re += br[l * 4 + m] + cr[l * 4 + m];
            im += bi[l * 4 + m] + ci[l * 4 + m];
        }
        sC0[l] = pk2(re, im);
    }
    // Tile load with index clamping (== reference's jnp.clip); |x| once per position
    for (int i = t; i < 143; i += BLOCK) {
        int g = base - HALO_L + i;
        g = min(max(g, 0), N - 1);
        float2 v = x[g];
        sx[i] = v;
        sr[i] = fsqrt_ap(fmaf(v.x, v.x, v.y * v.y));
    }
    __syncthreads();

    // warp-level split: warps 0-1 -> l in [0,4), warps 2-3 -> l in [4,8)
    const int j    = t & 63;
    const int half = t >> 6;
    const int l0   = half * 4;
    const int roff = 2 * j + 4 - 4 * half;   // tile idx of rr[0]  (n0 - 6 - 4h)
    const int xoff = 2 * j + 7 - 4 * half;   // tile idx of xa[0]  (n0 - 3 - 4h)

    float rr[11];
    float2 xa[5];
    #pragma unroll
    for (int i = 0; i < 11; i++) rr[i] = sr[roff + i];
    #pragma unroll
    for (int i = 0; i < 5; i++)  xa[i] = sx[xoff + i];

    float yr0 = 0.f, yi0 = 0.f, yr1 = 0.f, yi1 = 0.f;

    #pragma unroll
    for (int ll = 0; ll < 4; ll++) {
        const int l = l0 + ll;
        u64 seed = sC0[l];
        u64 w0 = seed, w1 = seed;
        #pragma unroll
        for (int e3 = 0; e3 < 7; e3++) {
            const ulonglong2* C = (const ulonglong2*)&sQ[(l * 7 + e3) * 8];
            ulonglong2 c01 = C[0], c23 = C[1], c45 = C[2], c67 = C[3];
            const int idx = 3 - ll + e3;          // compile-time (independent of half)
            u64 r0 = pk2(rr[idx], rr[idx]);
            u64 r1 = pk2(rr[idx + 1], rr[idx + 1]);
            u64 h0 = fma2(c67.y, r0, c67.x);      // c7*r + c6
            u64 h1 = fma2(c67.y, r1, c67.x);
            h0 = fma2(h0, r0, c45.y);  h1 = fma2(h1, r1, c45.y);
            h0 = fma2(h0, r0, c45.x);  h1 = fma2(h1, r1, c45.x);
            h0 = fma2(h0, r0, c23.y);  h1 = fma2(h1, r1, c23.y);
            h0 = fma2(h0, r0, c23.x);  h1 = fma2(h1, r1, c23.x);
            h0 = fma2(h0, r0, c01.y);  h1 = fma2(h1, r1, c01.y);
            w0 = fma2(h0, r0, w0);                // k=1..7 + accumulate
            w1 = fma2(h1, r1, w1);
        }
        float2 xl0 = xa[3 - ll];                  // carrier x[n0-l]
        float2 xl1 = xa[4 - ll];                  // carrier x[n0+1-l]
        float wr0, wi0, wr1, wi1;
        up2(w0, wr0, wi0);
        up2(w1, wr1, wi1);
        yr0 = fmaf(xl0.x, wr0, fmaf(-xl0.y, wi0, yr0));
        yi0 = fmaf(xl0.x, wi0, fmaf( xl0.y, wr0, yi0));
        yr1 = fmaf(xl1.x, wr1, fmaf(-xl1.y, wi1, yr1));
        yi1 = fmaf(xl1.x, wi1, fmaf( xl1.y, wr1, yi1));
    }

    if (half) sP[j] = make_float4(yr0, yi0, yr1, yi1);
    __syncthreads();
    if (!half) {
        float4 p = sP[j];
        int n0 = base + 2 * j;
        if (n0 + 1 < N) {
            ((float4*)y)[n0 >> 1] =
                make_float4(yr0 + p.x, yi0 + p.y, yr1 + p.z, yi1 + p.w);
        } else if (n0 < N) {
            y[n0] = make_float2(yr0 + p.x, yi0 + p.y);
        }
    }
}

extern "C" void kernel_launch(void* const* d_in, const int* in_sizes, int n_in,
                              void* d_out, int out_size) {
    const float2* x  = (const float2*)d_in[0];
    const float*  ar = (const float*)d_in[1];
    const float*  ai = (const float*)d_in[2];
    const float*  br = (const float*)d_in[3];
    const float*  bi = (const float*)d_in[4];
    const float*  cr = (const float*)d_in[5];
    const float*  ci = (const float*)d_in[6];
    float2* y = (float2*)d_out;
    int N = in_sizes[0] / 2;

    int grid = (N + OUTB - 1) / OUTB;
    gmp_kernel<<<grid, BLOCK>>>(x, ar, ai, br, bi, cr, ci, y, N);
}

// round 6
// speedup vs baseline: 1.0475x; 1.0475x over previous
#include <cuda_runtime.h>

#define BLOCK 128
#define OUTB  256                     // 2 outputs/thread -> grid 1024
#define HALO_L 10
#define TILE 272                      // need idx 0..268

typedef unsigned long long u64;

// table layout (ulonglong2[228]):
//   [0,224)   : Q[(l*7+e3)*4 + p]  packs coeffs k=2p (.x) and k=2p+1 (.y), each (re,im) b64
//   [224,228) : C0[l] pairs: elem .x = C0[2*i], .y = C0[2*i+1]
__device__ __align__(16) ulonglong2 g_tab[228];
__constant__ __align__(16) ulonglong2 c_tab[228];

static __device__ __forceinline__ u64 pk2(float a, float b) {
    u64 v; asm("mov.b64 %0,{%1,%2};" : "=l"(v) : "f"(a), "f"(b)); return v;
}
static __device__ __forceinline__ void up2(u64 v, float& a, float& b) {
    asm("mov.b64 {%0,%1},%2;" : "=f"(a), "=f"(b) : "l"(v));
}
static __device__ __forceinline__ u64 fma2(u64 a, u64 b, u64 c) {
    u64 d; asm("fma.rn.f32x2 %0,%1,%2,%3;" : "=l"(d) : "l"(a), "l"(b), "l"(c)); return d;
}
static __device__ __forceinline__ float fsqrt_ap(float x) {
    float r; asm("sqrt.approx.f32 %0,%1;" : "=f"(r) : "f"(x)); return r;
}

// Merged table: Q[l][e3][k], e3 = e+3, e in [-3,3]:
//   e=0  : a[k,l] + b[k,l,0] + c[k,l,0]
//   e=-m : b[k,l,m]   (envelope at n-l-m)
//   e=+m : c[k,l,m]   (envelope at n-l+m)
// C0[l] = sum_e3 Q[l,e3,0]  (seeds the per-l accumulator; k=0 term is constant in r)
__global__ void gmp_prep(const float* __restrict__ ar, const float* __restrict__ ai,
                         const float* __restrict__ br, const float* __restrict__ bi,
                         const float* __restrict__ cr, const float* __restrict__ ci) {
    int i = threadIdx.x;
    u64* gt = (u64*)g_tab;
    if (i < 448) {
        int k  = i & 7;
        int e3 = (i >> 3) % 7;
        int l  = i / 56;
        int kl = k * 8 + l;                 // a[k][l], row-major (8,8)
        float re, im;
        if (e3 == 3) {
            re = ar[kl] + br[kl * 4] + cr[kl * 4];
            im = ai[kl] + bi[kl * 4] + ci[kl * 4];
        } else if (e3 < 3) {
            int m = 3 - e3;
            re = br[kl * 4 + m]; im = bi[kl * 4 + m];
        } else {
            int m = e3 - 3;
            re = cr[kl * 4 + m]; im = ci[kl * 4 + m];
        }
        gt[(l * 7 + e3) * 8 + k] = pk2(re, im);
    } else if (i < 456) {
        int l = i - 448;
        float re = ar[l], im = ai[l];
        #pragma unroll
        for (int m = 0; m < 4; m++) {
            re += br[l * 4 + m] + cr[l * 4 + m];
            im += bi[l * 4 + m] + ci[l * 4 + m];
        }
        gt[448 + l] = pk2(re, im);
    }
}

__global__ __launch_bounds__(BLOCK)
void gmp_kernel(const float2* __restrict__ x, float2* __restrict__ y, int N) {
    __shared__ float2 sx[TILE];
    __shared__ u64 srr[TILE];

    const int t = threadIdx.x;
    const int base = blockIdx.x * OUTB;

    // Tile load with index clamping (== reference's jnp.clip); |x| packed once
    for (int i = t; i < 269; i += BLOCK) {
        int g = base - HALO_L + i;
        g = min(max(g, 0), N - 1);
        float2 v = x[g];
        sx[i] = v;
        float r = fsqrt_ap(fmaf(v.x, v.x, v.y * v.y));
        srr[i] = pk2(r, r);
    }
    __syncthreads();

    // rr[i] <-> envelope |x| at position n0-10+i   (n0 = base + 2t)
    u64 rr[15];
    #pragma unroll
    for (int i = 0; i < 15; i++) rr[i] = srr[2 * t + i];

    float yr0 = 0.f, yi0 = 0.f, yr1 = 0.f, yi1 = 0.f;
    const u64* C0 = (const u64*)&c_tab[224];

    #pragma unroll
    for (int l = 0; l < 8; l++) {
        u64 seed = C0[l];                    // LDC imm
        u64 w0 = seed, w1 = seed;
        #pragma unroll
        for (int e3 = 0; e3 < 7; e3++) {
            // coefficient pairs via constant memory, immediate offsets
            ulonglong2 c01 = c_tab[(l * 7 + e3) * 4 + 0];
            ulonglong2 c23 = c_tab[(l * 7 + e3) * 4 + 1];
            ulonglong2 c45 = c_tab[(l * 7 + e3) * 4 + 2];
            ulonglong2 c67 = c_tab[(l * 7 + e3) * 4 + 3];
            const int idx = 7 - l + e3;      // compile-time rr index (0..13)
            u64 r0 = rr[idx];
            u64 r1 = rr[idx + 1];
            u64 h0 = fma2(c67.y, r0, c67.x); // c7*r + c6
            u64 h1 = fma2(c67.y, r1, c67.x);
            h0 = fma2(h0, r0, c45.y);  h1 = fma2(h1, r1, c45.y);
            h0 = fma2(h0, r0, c45.x);  h1 = fma2(h1, r1, c45.x);
            h0 = fma2(h0, r0, c23.y);  h1 = fma2(h1, r1, c23.y);
            h0 = fma2(h0, r0, c23.x);  h1 = fma2(h1, r1, c23.x);
            h0 = fma2(h0, r0, c01.y);  h1 = fma2(h1, r1, c01.y);
            w0 = fma2(h0, r0, w0);           // k=1..7 done + accumulate
            w1 = fma2(h1, r1, w1);
        }
        float2 xl0 = sx[2 * t + 10 - l];     // carrier x[n0-l]
        float2 xl1 = sx[2 * t + 11 - l];     // carrier x[n0+1-l]
        float wr0, wi0, wr1, wi1;
        up2(w0, wr0, wi0);
        up2(w1, wr1, wi1);
        yr0 = fmaf(xl0.x, wr0, fmaf(-xl0.y, wi0, yr0));
        yi0 = fmaf(xl0.x, wi0, fmaf( xl0.y, wr0, yi0));
        yr1 = fmaf(xl1.x, wr1, fmaf(-xl1.y, wi1, yr1));
        yi1 = fmaf(xl1.x, wi1, fmaf( xl1.y, wr1, yi1));
    }

    int n0 = base + 2 * t;
    if (n0 + 1 < N) {
        ((float4*)y)[n0 >> 1] = make_float4(yr0, yi0, yr1, yi1);
    } else if (n0 < N) {
        y[n0] = make_float2(yr0, yi0);
    }
}

extern "C" void kernel_launch(void* const* d_in, const int* in_sizes, int n_in,
                              void* d_out, int out_size) {
    const float2* x  = (const float2*)d_in[0];
    const float*  ar = (const float*)d_in[1];
    const float*  ai = (const float*)d_in[2];
    const float*  br = (const float*)d_in[3];
    const float*  bi = (const float*)d_in[4];
    const float*  cr = (const float*)d_in[5];
    const float*  ci = (const float*)d_in[6];
    float2* y = (float2*)d_out;
    int N = in_sizes[0] / 2;

    gmp_prep<<<1, 512>>>(ar, ai, br, bi, cr, ci);

    static void* s_gtab = nullptr;
    if (!s_gtab) cudaGetSymbolAddress(&s_gtab, g_tab);
    cudaMemcpyToSymbolAsync(c_tab, s_gtab, sizeof(g_tab), 0,
                            cudaMemcpyDeviceToDevice, 0);

    int grid = (N + OUTB - 1) / OUTB;
    gmp_kernel<<<grid, BLOCK>>>(x, y, N);
}

// round 7
// speedup vs baseline: 1.1140x; 1.0636x over previous
#include <cuda_runtime.h>

#define BLOCK 128
#define OPT 4
#define OUTB (BLOCK * OPT)            // 512 outputs/block -> grid 512
#define HALO_L 10
#define TILE 528                      // need idx 0 .. 4*127+16 = 524

typedef unsigned long long u64;

// Constant table, ulonglong2[228]:
//   [0,224)   : Q[(l*7+e3)*4 + p] packs coeffs k=2p (.x), k=2p+1 (.y), each (re,im) b64
//   [224,228) : C0[l] seeds (u64 each, 8 total)
__constant__ __align__(16) ulonglong2 c_tab[228];

static __device__ __forceinline__ u64 pk2(float a, float b) {
    u64 v; asm("mov.b64 %0,{%1,%2};" : "=l"(v) : "f"(a), "f"(b)); return v;
}
static __device__ __forceinline__ void up2(u64 v, float& a, float& b) {
    asm("mov.b64 {%0,%1},%2;" : "=f"(a), "=f"(b) : "l"(v));
}
static __device__ __forceinline__ u64 fma2(u64 a, u64 b, u64 c) {
    u64 d; asm("fma.rn.f32x2 %0,%1,%2,%3;" : "=l"(d) : "l"(a), "l"(b), "l"(c)); return d;
}
static __device__ __forceinline__ float fsqrt_ap(float x) {
    float r; asm("sqrt.approx.f32 %0,%1;" : "=f"(r) : "f"(x)); return r;
}

// Merged table: Q[l][e3][k], e3 = e+3, e in [-3,3]:
//   e=0  : a[k,l] + b[k,l,0] + c[k,l,0]
//   e=-m : b[k,l,m]   (envelope at n-l-m)
//   e=+m : c[k,l,m]   (envelope at n-l+m)
// C0[l] = sum_e3 Q[l,e3,0]   (k=0 term is r-independent; seeds the accumulator)
// Writes DIRECTLY into c_tab's backing store; constant cache reloads at the
// next launch boundary.
__global__ void gmp_prep(u64* __restrict__ tab,
                         const float* __restrict__ ar, const float* __restrict__ ai,
                         const float* __restrict__ br, const float* __restrict__ bi,
                         const float* __restrict__ cr, const float* __restrict__ ci) {
    int i = threadIdx.x;
    if (i < 448) {
        int k  = i & 7;
        int e3 = (i >> 3) % 7;
        int l  = i / 56;
        int kl = k * 8 + l;                 // a[k][l], row-major (8,8)
        float re, im;
        if (e3 == 3) {
            re = ar[kl] + br[kl * 4] + cr[kl * 4];
            im = ai[kl] + bi[kl * 4] + ci[kl * 4];
        } else if (e3 < 3) {
            int m = 3 - e3;
            re = br[kl * 4 + m]; im = bi[kl * 4 + m];
        } else {
            int m = e3 - 3;
            re = cr[kl * 4 + m]; im = ci[kl * 4 + m];
        }
        tab[(l * 7 + e3) * 8 + k] = pk2(re, im);
    } else if (i < 456) {
        int l = i - 448;
        float re = ar[l], im = ai[l];
        #pragma unroll
        for (int m = 0; m < 4; m++) {
            re += br[l * 4 + m] + cr[l * 4 + m];
            im += bi[l * 4 + m] + ci[l * 4 + m];
        }
        tab[448 + l] = pk2(re, im);
    }
}

__global__ __launch_bounds__(BLOCK)
void gmp_kernel(const float2* __restrict__ x, float2* __restrict__ y, int N) {
    __shared__ float2 sx[TILE];
    __shared__ u64 srr[TILE];

    const int t = threadIdx.x;
    const int base = blockIdx.x * OUTB;

    // Tile load with index clamping (== reference's jnp.clip); |x| packed once
    for (int i = t; i < 525; i += BLOCK) {
        int g = base - HALO_L + i;
        g = min(max(g, 0), N - 1);
        float2 v = x[g];
        sx[i] = v;
        float r = fsqrt_ap(fmaf(v.x, v.x, v.y * v.y));
        srr[i] = pk2(r, r);
    }
    __syncthreads();

    // rr[i] <-> envelope |x| at n0-10+i, n0 = base + 4t  (17 u64, register-resident)
    u64 rr[17];
    #pragma unroll
    for (int i = 0; i < 17; i++) rr[i] = srr[4 * t + i];

    float yr[OPT] = {0.f, 0.f, 0.f, 0.f};
    float yi[OPT] = {0.f, 0.f, 0.f, 0.f};
    const u64* C0 = (const u64*)&c_tab[224];

    #pragma unroll
    for (int l = 0; l < 8; l++) {
        u64 seed = C0[l];                         // LDC imm
        u64 w[OPT];
        #pragma unroll
        for (int j = 0; j < OPT; j++) w[j] = seed;

        #pragma unroll
        for (int e3 = 0; e3 < 7; e3++) {
            ulonglong2 c01 = c_tab[(l * 7 + e3) * 4 + 0];   // LDC.128, imm offsets
            ulonglong2 c23 = c_tab[(l * 7 + e3) * 4 + 1];
            ulonglong2 c45 = c_tab[(l * 7 + e3) * 4 + 2];
            ulonglong2 c67 = c_tab[(l * 7 + e3) * 4 + 3];
            #pragma unroll
            for (int j = 0; j < OPT; j++) {
                u64 r = rr[j - l + e3 + 7];       // compile-time index, 0..16
                u64 h = fma2(c67.y, r, c67.x);    // c7*r + c6
                h = fma2(h, r, c45.y);            // *r + c5
                h = fma2(h, r, c45.x);            // *r + c4
                h = fma2(h, r, c23.y);            // *r + c3
                h = fma2(h, r, c23.x);            // *r + c2
                h = fma2(h, r, c01.y);            // *r + c1
                w[j] = fma2(h, r, w[j]);          // *r + accum (k=0 lives in seed)
            }
        }
        #pragma unroll
        for (int j = 0; j < OPT; j++) {
            float2 xl = sx[4 * t + 10 + j - l];   // carrier x[n0+j-l]
            float wr, wi; up2(w[j], wr, wi);
            yr[j] = fmaf(xl.x, wr, fmaf(-xl.y, wi, yr[j]));
            yi[j] = fmaf(xl.x, wi, fmaf( xl.y, wr, yi[j]));
        }
    }

    int n0 = base + 4 * t;
    if (n0 + 3 < N) {
        float4* y4 = (float4*)y;
        y4[(n0 >> 1)]     = make_float4(yr[0], yi[0], yr[1], yi[1]);
        y4[(n0 >> 1) + 1] = make_float4(yr[2], yi[2], yr[3], yi[3]);
    } else {
        #pragma unroll
        for (int j = 0; j < OPT; j++)
            if (n0 + j < N) y[n0 + j] = make_float2(yr[j], yi[j]);
    }
}

extern "C" void kernel_launch(void* const* d_in, const int* in_sizes, int n_in,
                              void* d_out, int out_size) {
    const float2* x  = (const float2*)d_in[0];
    const float*  ar = (const float*)d_in[1];
    const float*  ai = (const float*)d_in[2];
    const float*  br = (const float*)d_in[3];
    const float*  bi = (const float*)d_in[4];
    const float*  cr = (const float*)d_in[5];
    const float*  ci = (const float*)d_in[6];
    float2* y = (float2*)d_out;
    int N = in_sizes[0] / 2;

    static u64* tab = nullptr;
    if (!tab) {
        void* p = nullptr;
        cudaGetSymbolAddress(&p, c_tab);
        tab = (u64*)p;
    }
    gmp_prep<<<1, 512>>>(tab, ar, ai, br, bi, cr, ci);

    int grid = (N + OUTB - 1) / OUTB;
    gmp_kernel<<<grid, BLOCK>>>(x, y, N);
}